// round 2
// baseline (speedup 1.0000x reference)
#include <cuda_runtime.h>
#include <math.h>

#define BB 4
#define SS 4096
#define DD 256
#define HH 4
#define HD 64
#define NN (BB*SS)
#define INV_TEMP 0.125f
#define LN_EPS 1e-5f

// Scratch (allocation-free): 8 x 16 MiB device globals.
__device__ float g_xn[NN*DD];
__device__ float g_q[NN*DD];
__device__ float g_k[NN*DD];
__device__ float g_v[NN*DD];
__device__ float g_att[NN*DD];
__device__ float g_xt[NN*DD];
__device__ float g_h[NN*DD];
__device__ float g_a1[NN*DD];

__device__ __forceinline__ float warp_sum(float v) {
    #pragma unroll
    for (int o = 16; o; o >>= 1) v += __shfl_xor_sync(0xffffffffu, v, o);
    return v;
}

// LayerNorm (optionally fused residual add). One block per row, 256 threads.
__global__ void ln_kernel(const float* __restrict__ x, const float* __restrict__ res,
                          const float* __restrict__ g, const float* __restrict__ b,
                          float* __restrict__ xt_out, float* __restrict__ y) {
    int row = blockIdx.x;
    int t = threadIdx.x;
    size_t i = (size_t)row * DD + t;
    float v = x[i];
    if (res) v += res[i];
    if (xt_out) xt_out[i] = v;

    __shared__ float red1[8], red2[8];
    float s1 = warp_sum(v);
    float s2 = warp_sum(v * v);
    if ((t & 31) == 0) { red1[t >> 5] = s1; red2[t >> 5] = s2; }
    __syncthreads();
    float tot = 0.f, tot2 = 0.f;
    #pragma unroll
    for (int w = 0; w < 8; w++) { tot += red1[w]; tot2 += red2[w]; }
    float mu = tot * (1.f / DD);
    float var = tot2 * (1.f / DD) - mu * mu;
    float rstd = rsqrtf(var + LN_EPS);
    y[i] = (v - mu) * rstd * g[t] + b[t];
}

// C[M,256] = A[M,256] @ W[256,256]^T  (torch Linear). NT GEMM.
// BM=128, BN=64, BK=16; 256 threads; 8x4 per-thread microtile (FMA-bound).
// epi: 0 = plain store; 1 = +bias, relu; 2 = +bias +res
__global__ void gemm_nt(const float* __restrict__ A, const float* __restrict__ W,
                        const float* __restrict__ bias, const float* __restrict__ res,
                        float* __restrict__ C, int epi) {
    __shared__ float As[128 * 17];
    __shared__ float Bs[64 * 17];
    int tid = threadIdx.x;
    int bm = blockIdx.y * 128, bn = blockIdx.x * 64;
    int tr = (tid >> 4) * 8;      // 0..120
    int tc = (tid & 15) * 4;      // 0..60

    float acc[8][4];
    #pragma unroll
    for (int i = 0; i < 8; i++)
        #pragma unroll
        for (int j = 0; j < 4; j++) acc[i][j] = 0.f;

    for (int k0 = 0; k0 < DD; k0 += 16) {
        // A tile: 128x16 floats = 512 float4, 2 per thread
        #pragma unroll
        for (int l = 0; l < 2; l++) {
            int idx = tid + l * 256;
            int m = idx >> 2, k4 = (idx & 3) * 4;
            float4 tv = *(const float4*)&A[(size_t)(bm + m) * DD + k0 + k4];
            As[m * 17 + k4 + 0] = tv.x;
            As[m * 17 + k4 + 1] = tv.y;
            As[m * 17 + k4 + 2] = tv.z;
            As[m * 17 + k4 + 3] = tv.w;
        }
        // W tile: 64x16 floats = 256 float4, 1 per thread
        {
            int n = tid >> 2, k4 = (tid & 3) * 4;
            float4 tv = *(const float4*)&W[(size_t)(bn + n) * DD + k0 + k4];
            Bs[n * 17 + k4 + 0] = tv.x;
            Bs[n * 17 + k4 + 1] = tv.y;
            Bs[n * 17 + k4 + 2] = tv.z;
            Bs[n * 17 + k4 + 3] = tv.w;
        }
        __syncthreads();
        #pragma unroll
        for (int kk = 0; kk < 16; kk++) {
            float a[8], bv[4];
            #pragma unroll
            for (int i = 0; i < 8; i++) a[i] = As[(tr + i) * 17 + kk];
            #pragma unroll
            for (int j = 0; j < 4; j++) bv[j] = Bs[(tc + j) * 17 + kk];
            #pragma unroll
            for (int i = 0; i < 8; i++)
                #pragma unroll
                for (int j = 0; j < 4; j++) acc[i][j] += a[i] * bv[j];
        }
        __syncthreads();
    }

    #pragma unroll
    for (int i = 0; i < 8; i++) {
        int m = bm + tr + i;
        float4 o;
        float* po = &o.x;
        #pragma unroll
        for (int j = 0; j < 4; j++) {
            int n = bn + tc + j;              // FIXED: include bn
            float v = acc[i][j];
            if (epi >= 1) v += bias[n];
            if (epi == 1) v = fmaxf(v, 0.f);
            po[j] = v;
        }
        if (epi == 2) {
            float4 rv = *(const float4*)&res[(size_t)m * DD + bn + tc];   // FIXED
            o.x += rv.x; o.y += rv.y; o.z += rv.z; o.w += rv.w;
        }
        *(float4*)&C[(size_t)m * DD + bn + tc] = o;                       // FIXED
    }
}

// Flash attention, causal. One block per (q-tile of 64, b*h). 256 threads.
// thread: r = tid>>2 (q row in tile), q4 = tid&3.
// Score phase: j = q4 + 4*jj (interleaved -> conflict-free LDS.128).
// PV phase: c = q4*16 + cc (contiguous -> vectorized V reads).
#define SP 68  // smem row stride (floats), 16B-aligned rows, conflict-friendly
__global__ void attn_kernel(const float* __restrict__ q, const float* __restrict__ k,
                            const float* __restrict__ v, float* __restrict__ att) {
    extern __shared__ float sm[];
    float* Qs = sm;
    float* Ks = sm + 64 * SP;
    float* Vs = sm + 2 * 64 * SP;
    float* Ps = sm + 3 * 64 * SP;

    int bh = blockIdx.y;
    int b = bh >> 2, h = bh & 3;
    int qt = 63 - blockIdx.x;  // longest blocks launch first
    int tid = threadIdx.x;
    int r = tid >> 2;
    int q4 = tid & 3;

    const float* qbase = q + (size_t)b * SS * DD + h * HD;
    const float* kbase = k + (size_t)b * SS * DD + h * HD;
    const float* vbase = v + (size_t)b * SS * DD + h * HD;

    // Load Q tile (scaled by 1/TEMP): 64 rows x 64 dims = 1024 float4
    for (int l = tid; l < 1024; l += 256) {
        int rr = l >> 4, d4 = (l & 15) * 4;
        float4 tv = *(const float4*)&qbase[(size_t)(qt * 64 + rr) * DD + d4];
        Qs[rr * SP + d4 + 0] = tv.x * INV_TEMP;
        Qs[rr * SP + d4 + 1] = tv.y * INV_TEMP;
        Qs[rr * SP + d4 + 2] = tv.z * INV_TEMP;
        Qs[rr * SP + d4 + 3] = tv.w * INV_TEMP;
    }

    float acc[16];
    #pragma unroll
    for (int c = 0; c < 16; c++) acc[c] = 0.f;
    float m_i = -INFINITY, l_i = 0.f;

    __syncthreads();

    for (int kt = 0; kt <= qt; kt++) {
        // Load K and V tiles
        for (int l = tid; l < 1024; l += 256) {
            int rr = l >> 4, d4 = (l & 15) * 4;
            size_t gidx = (size_t)(kt * 64 + rr) * DD + d4;
            float4 kv = *(const float4*)&kbase[gidx];
            float4 vv = *(const float4*)&vbase[gidx];
            Ks[rr * SP + d4 + 0] = kv.x; Ks[rr * SP + d4 + 1] = kv.y;
            Ks[rr * SP + d4 + 2] = kv.z; Ks[rr * SP + d4 + 3] = kv.w;
            Vs[rr * SP + d4 + 0] = vv.x; Vs[rr * SP + d4 + 1] = vv.y;
            Vs[rr * SP + d4 + 2] = vv.z; Vs[rr * SP + d4 + 3] = vv.w;
        }
        __syncthreads();

        // Scores: s[jj] = q_row . k_{q4+4jj}
        float s[16];
        #pragma unroll
        for (int jj = 0; jj < 16; jj++) s[jj] = 0.f;
        #pragma unroll
        for (int d0 = 0; d0 < 64; d0 += 4) {
            float4 qv = *(const float4*)&Qs[r * SP + d0];
            #pragma unroll
            for (int jj = 0; jj < 16; jj++) {
                float4 kv = *(const float4*)&Ks[(q4 + (jj << 2)) * SP + d0];
                s[jj] += qv.x * kv.x + qv.y * kv.y + qv.z * kv.z + qv.w * kv.w;
            }
        }

        bool diag = (kt == qt);
        float mx = -INFINITY;
        #pragma unroll
        for (int jj = 0; jj < 16; jj++) {
            int j = q4 + (jj << 2);
            if (diag && j > r) s[jj] = -INFINITY;
            mx = fmaxf(mx, s[jj]);
        }
        mx = fmaxf(mx, __shfl_xor_sync(0xffffffffu, mx, 1));
        mx = fmaxf(mx, __shfl_xor_sync(0xffffffffu, mx, 2));
        float m_new = fmaxf(m_i, mx);
        float alpha = __expf(m_i - m_new);

        float lsum = 0.f;
        #pragma unroll
        for (int jj = 0; jj < 16; jj++) {
            float p = __expf(s[jj] - m_new);
            lsum += p;
            Ps[r * SP + q4 + (jj << 2)] = p;
        }
        lsum += __shfl_xor_sync(0xffffffffu, lsum, 1);
        lsum += __shfl_xor_sync(0xffffffffu, lsum, 2);
        l_i = l_i * alpha + lsum;
        m_i = m_new;
        #pragma unroll
        for (int c = 0; c < 16; c++) acc[c] *= alpha;

        // Ps row r is produced and consumed entirely within this warp.
        __syncwarp();

        // PV: acc[c] += sum_j P[r][j] * V[j][q4*16 + c]
        #pragma unroll 4
        for (int j = 0; j < 64; j++) {
            float p = Ps[r * SP + j];
            const float* vr = &Vs[j * SP + (q4 << 4)];
            float4 v0 = *(const float4*)&vr[0];
            float4 v1 = *(const float4*)&vr[4];
            float4 v2 = *(const float4*)&vr[8];
            float4 v3 = *(const float4*)&vr[12];
            acc[0]  += p * v0.x; acc[1]  += p * v0.y; acc[2]  += p * v0.z; acc[3]  += p * v0.w;
            acc[4]  += p * v1.x; acc[5]  += p * v1.y; acc[6]  += p * v1.z; acc[7]  += p * v1.w;
            acc[8]  += p * v2.x; acc[9]  += p * v2.y; acc[10] += p * v2.z; acc[11] += p * v2.w;
            acc[12] += p * v3.x; acc[13] += p * v3.y; acc[14] += p * v3.z; acc[15] += p * v3.w;
        }
        __syncthreads();
    }

    float inv = 1.f / l_i;
    float* obase = att + (size_t)b * SS * DD + h * HD;
    size_t orow = (size_t)(qt * 64 + r) * DD + (q4 << 4);
    #pragma unroll
    for (int c4 = 0; c4 < 4; c4++) {
        float4 o = make_float4(acc[c4 * 4 + 0] * inv, acc[c4 * 4 + 1] * inv,
                               acc[c4 * 4 + 2] * inv, acc[c4 * 4 + 3] * inv);
        *(float4*)&obase[orow + c4 * 4] = o;
    }
}

#define SMEM_ATTN (4 * 64 * SP * 4)

extern "C" void kernel_launch(void* const* d_in, const int* in_sizes, int n_in,
                              void* d_out, int out_size) {
    const float* x   = (const float*)d_in[0];
    const float* Wq  = (const float*)d_in[1];
    const float* Wk  = (const float*)d_in[2];
    const float* Wv  = (const float*)d_in[3];
    const float* g1  = (const float*)d_in[4];
    const float* b1  = (const float*)d_in[5];
    const float* g2  = (const float*)d_in[6];
    const float* b2  = (const float*)d_in[7];
    const float* W1  = (const float*)d_in[8];
    const float* bf1 = (const float*)d_in[9];
    const float* W2  = (const float*)d_in[10];
    const float* bf2 = (const float*)d_in[11];
    float* out = (float*)d_out;

    float *xn, *q, *k, *v, *att, *xt, *h, *a1;
    cudaGetSymbolAddress((void**)&xn,  g_xn);
    cudaGetSymbolAddress((void**)&q,   g_q);
    cudaGetSymbolAddress((void**)&k,   g_k);
    cudaGetSymbolAddress((void**)&v,   g_v);
    cudaGetSymbolAddress((void**)&att, g_att);
    cudaGetSymbolAddress((void**)&xt,  g_xt);
    cudaGetSymbolAddress((void**)&h,   g_h);
    cudaGetSymbolAddress((void**)&a1,  g_a1);

    cudaFuncSetAttribute(attn_kernel, cudaFuncAttributeMaxDynamicSharedMemorySize, SMEM_ATTN);

    // 1. xn = LN(x)
    ln_kernel<<<NN, 256>>>(x, nullptr, g1, b1, nullptr, xn);
    // 2. QKV projections
    gemm_nt<<<dim3(DD / 64, NN / 128), 256>>>(xn, Wq, nullptr, nullptr, q, 0);
    gemm_nt<<<dim3(DD / 64, NN / 128), 256>>>(xn, Wk, nullptr, nullptr, k, 0);
    gemm_nt<<<dim3(DD / 64, NN / 128), 256>>>(xn, Wv, nullptr, nullptr, v, 0);
    // 3. causal flash attention
    attn_kernel<<<dim3(SS / 64, BB * HH), 256, SMEM_ATTN>>>(q, k, v, att);
    // 4. xt = x + att; h = LN(xt)
    ln_kernel<<<NN, 256>>>(x, att, g2, b2, xt, h);
    // 5. a1 = relu(h @ W1^T + bf1)
    gemm_nt<<<dim3(DD / 64, NN / 128), 256>>>(h, W1, bf1, nullptr, a1, 1);
    // 6. out = xt + a1 @ W2^T + bf2
    gemm_nt<<<dim3(DD / 64, NN / 128), 256>>>(a1, W2, bf2, xt, out, 2);
}

// round 3
// speedup vs baseline: 2.5914x; 2.5914x over previous
#include <cuda_runtime.h>
#include <math.h>

#define BB 4
#define SS 4096
#define DD 256
#define HH 4
#define HD 64
#define NN (BB*SS)
#define INV_TEMP 0.125f
#define LN_EPS 1e-5f

// Scratch (allocation-free): 8 x 16 MiB device globals.
__device__ float g_xn[NN*DD];
__device__ float g_q[NN*DD];
__device__ float g_k[NN*DD];
__device__ float g_v[NN*DD];
__device__ float g_att[NN*DD];
__device__ float g_xt[NN*DD];
__device__ float g_h[NN*DD];
__device__ float g_a1[NN*DD];

__device__ __forceinline__ float warp_sum(float v) {
    #pragma unroll
    for (int o = 16; o; o >>= 1) v += __shfl_xor_sync(0xffffffffu, v, o);
    return v;
}

// LayerNorm (optionally fused residual add). One block per row, 256 threads.
__global__ void ln_kernel(const float* __restrict__ x, const float* __restrict__ res,
                          const float* __restrict__ g, const float* __restrict__ b,
                          float* __restrict__ xt_out, float* __restrict__ y) {
    int row = blockIdx.x;
    int t = threadIdx.x;
    size_t i = (size_t)row * DD + t;
    float v = x[i];
    if (res) v += res[i];
    if (xt_out) xt_out[i] = v;

    __shared__ float red1[8], red2[8];
    float s1 = warp_sum(v);
    float s2 = warp_sum(v * v);
    if ((t & 31) == 0) { red1[t >> 5] = s1; red2[t >> 5] = s2; }
    __syncthreads();
    float tot = 0.f, tot2 = 0.f;
    #pragma unroll
    for (int w = 0; w < 8; w++) { tot += red1[w]; tot2 += red2[w]; }
    float mu = tot * (1.f / DD);
    float var = tot2 * (1.f / DD) - mu * mu;
    float rstd = rsqrtf(var + LN_EPS);
    y[i] = (v - mu) * rstd * g[t] + b[t];
}

// C[M,256] = A[M,256] @ W[256,256]^T  (torch Linear). NT GEMM.
// BM=128, BN=64, BK=16; 256 threads; 8x4 per-thread microtile (FMA-bound).
// epi: 0 = plain store; 1 = +bias, relu; 2 = +bias +res
__global__ void gemm_nt(const float* __restrict__ A, const float* __restrict__ W,
                        const float* __restrict__ bias, const float* __restrict__ res,
                        float* __restrict__ C, int epi) {
    __shared__ float As[128 * 17];
    __shared__ float Bs[64 * 17];
    int tid = threadIdx.x;
    int bm = blockIdx.y * 128, bn = blockIdx.x * 64;
    int tr = (tid >> 4) * 8;      // 0..120
    int tc = (tid & 15) * 4;      // 0..60

    float acc[8][4];
    #pragma unroll
    for (int i = 0; i < 8; i++)
        #pragma unroll
        for (int j = 0; j < 4; j++) acc[i][j] = 0.f;

    for (int k0 = 0; k0 < DD; k0 += 16) {
        #pragma unroll
        for (int l = 0; l < 2; l++) {
            int idx = tid + l * 256;
            int m = idx >> 2, k4 = (idx & 3) * 4;
            float4 tv = *(const float4*)&A[(size_t)(bm + m) * DD + k0 + k4];
            As[m * 17 + k4 + 0] = tv.x;
            As[m * 17 + k4 + 1] = tv.y;
            As[m * 17 + k4 + 2] = tv.z;
            As[m * 17 + k4 + 3] = tv.w;
        }
        {
            int n = tid >> 2, k4 = (tid & 3) * 4;
            float4 tv = *(const float4*)&W[(size_t)(bn + n) * DD + k0 + k4];
            Bs[n * 17 + k4 + 0] = tv.x;
            Bs[n * 17 + k4 + 1] = tv.y;
            Bs[n * 17 + k4 + 2] = tv.z;
            Bs[n * 17 + k4 + 3] = tv.w;
        }
        __syncthreads();
        #pragma unroll
        for (int kk = 0; kk < 16; kk++) {
            float a[8], bv[4];
            #pragma unroll
            for (int i = 0; i < 8; i++) a[i] = As[(tr + i) * 17 + kk];
            #pragma unroll
            for (int j = 0; j < 4; j++) bv[j] = Bs[(tc + j) * 17 + kk];
            #pragma unroll
            for (int i = 0; i < 8; i++)
                #pragma unroll
                for (int j = 0; j < 4; j++) acc[i][j] += a[i] * bv[j];
        }
        __syncthreads();
    }

    #pragma unroll
    for (int i = 0; i < 8; i++) {
        int m = bm + tr + i;
        float4 o;
        float* po = &o.x;
        #pragma unroll
        for (int j = 0; j < 4; j++) {
            int n = bn + tc + j;
            float v = acc[i][j];
            if (epi >= 1) v += bias[n];
            if (epi == 1) v = fmaxf(v, 0.f);
            po[j] = v;
        }
        if (epi == 2) {
            float4 rv = *(const float4*)&res[(size_t)m * DD + bn + tc];
            o.x += rv.x; o.y += rv.y; o.z += rv.z; o.w += rv.w;
        }
        *(float4*)&C[(size_t)m * DD + bn + tc] = o;
    }
}

// Flash attention, causal. One block per (64-row q-tile, b*h). 256 threads.
// Register-blocked 4x4 micro-tile: thread (ty=tid/16, tx=tid%16).
//   rows:       R = ty*4 + rr            (rr = 0..3)
//   score cols: j = tx + 16*c            (interleaved -> conflict-free K LDS.128)
//   PV cols:    c = tx*4 + cc            (contiguous  -> vectorized V LDS.128)
// Q/P loads are half-warp broadcasts; P round-trips smem under __syncwarp only.
#define SP 68  // smem row stride (floats): 272B => tx*272 hits 16 distinct 16B groups mod 128B
__global__ void attn_kernel(const float* __restrict__ q, const float* __restrict__ k,
                            const float* __restrict__ v, float* __restrict__ att) {
    extern __shared__ float sm[];
    float* Qs = sm;
    float* Ks = sm + 64 * SP;
    float* Vs = sm + 2 * 64 * SP;
    float* Ps = sm + 3 * 64 * SP;

    int bh = blockIdx.y;
    int b = bh >> 2, h = bh & 3;
    int qt = 63 - blockIdx.x;  // longest blocks launch first
    int tid = threadIdx.x;
    int ty = tid >> 4;         // 0..15 -> 4-row group
    int tx = tid & 15;         // 0..15

    const float* qbase = q + (size_t)b * SS * DD + h * HD;
    const float* kbase = k + (size_t)b * SS * DD + h * HD;
    const float* vbase = v + (size_t)b * SS * DD + h * HD;

    // Load Q tile (scaled by 1/TEMP): 64 rows x 64 dims = 1024 float4
    for (int l = tid; l < 1024; l += 256) {
        int rr = l >> 4, d4 = (l & 15) * 4;
        float4 tv = *(const float4*)&qbase[(size_t)(qt * 64 + rr) * DD + d4];
        Qs[rr * SP + d4 + 0] = tv.x * INV_TEMP;
        Qs[rr * SP + d4 + 1] = tv.y * INV_TEMP;
        Qs[rr * SP + d4 + 2] = tv.z * INV_TEMP;
        Qs[rr * SP + d4 + 3] = tv.w * INV_TEMP;
    }

    float acc[4][4];
    float m_i[4], l_i[4];
    #pragma unroll
    for (int rr = 0; rr < 4; rr++) {
        m_i[rr] = -INFINITY; l_i[rr] = 0.f;
        #pragma unroll
        for (int cc = 0; cc < 4; cc++) acc[rr][cc] = 0.f;
    }

    __syncthreads();

    for (int kt = 0; kt <= qt; kt++) {
        // Load K and V tiles
        for (int l = tid; l < 1024; l += 256) {
            int rr = l >> 4, d4 = (l & 15) * 4;
            size_t gidx = (size_t)(kt * 64 + rr) * DD + d4;
            float4 kv = *(const float4*)&kbase[gidx];
            float4 vv = *(const float4*)&vbase[gidx];
            Ks[rr * SP + d4 + 0] = kv.x; Ks[rr * SP + d4 + 1] = kv.y;
            Ks[rr * SP + d4 + 2] = kv.z; Ks[rr * SP + d4 + 3] = kv.w;
            Vs[rr * SP + d4 + 0] = vv.x; Vs[rr * SP + d4 + 1] = vv.y;
            Vs[rr * SP + d4 + 2] = vv.z; Vs[rr * SP + d4 + 3] = vv.w;
        }
        __syncthreads();

        // Scores: s[rr][c] = q_{ty*4+rr} . k_{tx+16c}
        float s[4][4];
        #pragma unroll
        for (int rr = 0; rr < 4; rr++)
            #pragma unroll
            for (int c = 0; c < 4; c++) s[rr][c] = 0.f;

        #pragma unroll
        for (int d0 = 0; d0 < 64; d0 += 4) {
            float4 qv[4], kv[4];
            #pragma unroll
            for (int rr = 0; rr < 4; rr++)
                qv[rr] = *(const float4*)&Qs[(ty * 4 + rr) * SP + d0];
            #pragma unroll
            for (int c = 0; c < 4; c++)
                kv[c] = *(const float4*)&Ks[(tx + 16 * c) * SP + d0];
            #pragma unroll
            for (int rr = 0; rr < 4; rr++)
                #pragma unroll
                for (int c = 0; c < 4; c++) {
                    s[rr][c] += qv[rr].x * kv[c].x + qv[rr].y * kv[c].y
                              + qv[rr].z * kv[c].z + qv[rr].w * kv[c].w;
                }
        }

        bool diag = (kt == qt);
        #pragma unroll
        for (int rr = 0; rr < 4; rr++) {
            int row = ty * 4 + rr;
            float mx = -INFINITY;
            #pragma unroll
            for (int c = 0; c < 4; c++) {
                int j = tx + 16 * c;
                if (diag && j > row) s[rr][c] = -INFINITY;
                mx = fmaxf(mx, s[rr][c]);
            }
            // reduce over the 16 threads sharing this row (same half-warp)
            mx = fmaxf(mx, __shfl_xor_sync(0xffffffffu, mx, 1));
            mx = fmaxf(mx, __shfl_xor_sync(0xffffffffu, mx, 2));
            mx = fmaxf(mx, __shfl_xor_sync(0xffffffffu, mx, 4));
            mx = fmaxf(mx, __shfl_xor_sync(0xffffffffu, mx, 8));
            float m_new = fmaxf(m_i[rr], mx);
            float alpha = __expf(m_i[rr] - m_new);

            float lsum = 0.f;
            #pragma unroll
            for (int c = 0; c < 4; c++) {
                float p = __expf(s[rr][c] - m_new);
                lsum += p;
                Ps[row * SP + tx + 16 * c] = p;
            }
            lsum += __shfl_xor_sync(0xffffffffu, lsum, 1);
            lsum += __shfl_xor_sync(0xffffffffu, lsum, 2);
            lsum += __shfl_xor_sync(0xffffffffu, lsum, 4);
            lsum += __shfl_xor_sync(0xffffffffu, lsum, 8);
            l_i[rr] = l_i[rr] * alpha + lsum;
            m_i[rr] = m_new;
            #pragma unroll
            for (int cc = 0; cc < 4; cc++) acc[rr][cc] *= alpha;
        }

        // P rows for this thread are produced & consumed within the same warp.
        __syncwarp();

        // PV: acc[rr][cc] += sum_j P[ty*4+rr][j] * V[j][tx*4+cc]
        #pragma unroll
        for (int j0 = 0; j0 < 64; j0 += 4) {
            float4 pv[4], vv[4];
            #pragma unroll
            for (int rr = 0; rr < 4; rr++)
                pv[rr] = *(const float4*)&Ps[(ty * 4 + rr) * SP + j0];
            #pragma unroll
            for (int jj = 0; jj < 4; jj++)
                vv[jj] = *(const float4*)&Vs[(j0 + jj) * SP + tx * 4];
            #pragma unroll
            for (int rr = 0; rr < 4; rr++) {
                const float* pr = &pv[rr].x;
                #pragma unroll
                for (int jj = 0; jj < 4; jj++) {
                    float p = pr[jj];
                    acc[rr][0] += p * vv[jj].x;
                    acc[rr][1] += p * vv[jj].y;
                    acc[rr][2] += p * vv[jj].z;
                    acc[rr][3] += p * vv[jj].w;
                }
            }
        }
        __syncthreads();
    }

    float* obase = att + (size_t)b * SS * DD + h * HD;
    #pragma unroll
    for (int rr = 0; rr < 4; rr++) {
        float inv = 1.f / l_i[rr];
        size_t orow = (size_t)(qt * 64 + ty * 4 + rr) * DD + tx * 4;
        float4 o = make_float4(acc[rr][0] * inv, acc[rr][1] * inv,
                               acc[rr][2] * inv, acc[rr][3] * inv);
        *(float4*)&obase[orow] = o;
    }
}

#define SMEM_ATTN (4 * 64 * SP * 4)

extern "C" void kernel_launch(void* const* d_in, const int* in_sizes, int n_in,
                              void* d_out, int out_size) {
    const float* x   = (const float*)d_in[0];
    const float* Wq  = (const float*)d_in[1];
    const float* Wk  = (const float*)d_in[2];
    const float* Wv  = (const float*)d_in[3];
    const float* g1  = (const float*)d_in[4];
    const float* b1  = (const float*)d_in[5];
    const float* g2  = (const float*)d_in[6];
    const float* b2  = (const float*)d_in[7];
    const float* W1  = (const float*)d_in[8];
    const float* bf1 = (const float*)d_in[9];
    const float* W2  = (const float*)d_in[10];
    const float* bf2 = (const float*)d_in[11];
    float* out = (float*)d_out;

    float *xn, *q, *k, *v, *att, *xt, *h, *a1;
    cudaGetSymbolAddress((void**)&xn,  g_xn);
    cudaGetSymbolAddress((void**)&q,   g_q);
    cudaGetSymbolAddress((void**)&k,   g_k);
    cudaGetSymbolAddress((void**)&v,   g_v);
    cudaGetSymbolAddress((void**)&att, g_att);
    cudaGetSymbolAddress((void**)&xt,  g_xt);
    cudaGetSymbolAddress((void**)&h,   g_h);
    cudaGetSymbolAddress((void**)&a1,  g_a1);

    cudaFuncSetAttribute(attn_kernel, cudaFuncAttributeMaxDynamicSharedMemorySize, SMEM_ATTN);

    // 1. xn = LN(x)
    ln_kernel<<<NN, 256>>>(x, nullptr, g1, b1, nullptr, xn);
    // 2. QKV projections
    gemm_nt<<<dim3(DD / 64, NN / 128), 256>>>(xn, Wq, nullptr, nullptr, q, 0);
    gemm_nt<<<dim3(DD / 64, NN / 128), 256>>>(xn, Wk, nullptr, nullptr, k, 0);
    gemm_nt<<<dim3(DD / 64, NN / 128), 256>>>(xn, Wv, nullptr, nullptr, v, 0);
    // 3. causal flash attention
    attn_kernel<<<dim3(SS / 64, BB * HH), 256, SMEM_ATTN>>>(q, k, v, att);
    // 4. xt = x + att; h = LN(xt)
    ln_kernel<<<NN, 256>>>(x, att, g2, b2, xt, h);
    // 5. a1 = relu(h @ W1^T + bf1)
    gemm_nt<<<dim3(DD / 64, NN / 128), 256>>>(h, W1, bf1, nullptr, a1, 1);
    // 6. out = xt + a1 @ W2^T + bf2
    gemm_nt<<<dim3(DD / 64, NN / 128), 256>>>(a1, W2, bf2, xt, out, 2);
}

// round 7
// speedup vs baseline: 2.7416x; 1.0579x over previous
#include <cuda_runtime.h>
#include <math.h>
#include <stdint.h>

#define BB 4
#define SS 4096
#define DD 256
#define HH 4
#define HD 64
#define NN (BB*SS)
#define INV_TEMP 0.125f
#define LN_EPS 1e-5f

typedef unsigned long long ull;

// Scratch (allocation-free): 8 x 16 MiB device globals.
__device__ float g_xn[NN*DD];
__device__ float g_q[NN*DD];
__device__ float g_k[NN*DD];
__device__ float g_v[NN*DD];
__device__ float g_att[NN*DD];
__device__ float g_xt[NN*DD];
__device__ float g_h[NN*DD];
__device__ float g_a1[NN*DD];

// ---- packed f32x2 helpers (Blackwell base-ISA; 2 fp32 per FMA-pipe issue) ----
__device__ __forceinline__ ull ffma2(ull a, ull b, ull c) {
    ull d; asm("fma.rn.f32x2 %0, %1, %2, %3;" : "=l"(d) : "l"(a), "l"(b), "l"(c)); return d;
}
__device__ __forceinline__ ull fmul2(ull a, ull b) {
    ull d; asm("mul.rn.f32x2 %0, %1, %2;" : "=l"(d) : "l"(a), "l"(b)); return d;
}
__device__ __forceinline__ ull pack2(float lo, float hi) {
    ull d; asm("mov.b64 %0, {%1, %2};" : "=l"(d) : "f"(lo), "f"(hi)); return d;
}
__device__ __forceinline__ void unpack2(ull v, float& lo, float& hi) {
    asm("mov.b64 {%0, %1}, %2;" : "=f"(lo), "=f"(hi) : "l"(v));
}
__device__ __forceinline__ float hsum2(ull v) {
    float lo, hi; unpack2(v, lo, hi); return lo + hi;
}

__device__ __forceinline__ float warp_sum(float v) {
    #pragma unroll
    for (int o = 16; o; o >>= 1) v += __shfl_xor_sync(0xffffffffu, v, o);
    return v;
}

// LayerNorm (optionally fused residual add). One block per row, 256 threads.
__global__ void ln_kernel(const float* __restrict__ x, const float* __restrict__ res,
                          const float* __restrict__ g, const float* __restrict__ b,
                          float* __restrict__ xt_out, float* __restrict__ y) {
    int row = blockIdx.x;
    int t = threadIdx.x;
    size_t i = (size_t)row * DD + t;
    float v = x[i];
    if (res) v += res[i];
    if (xt_out) xt_out[i] = v;

    __shared__ float red1[8], red2[8];
    float s1 = warp_sum(v);
    float s2 = warp_sum(v * v);
    if ((t & 31) == 0) { red1[t >> 5] = s1; red2[t >> 5] = s2; }
    __syncthreads();
    float tot = 0.f, tot2 = 0.f;
    #pragma unroll
    for (int w = 0; w < 8; w++) { tot += red1[w]; tot2 += red2[w]; }
    float mu = tot * (1.f / DD);
    float var = tot2 * (1.f / DD) - mu * mu;
    float rstd = rsqrtf(var + LN_EPS);
    y[i] = (v - mu) * rstd * g[t] + b[t];
}

// C[M,256] = A[M,256] @ W[256,256]^T  (torch Linear). NT GEMM, FFMA2 k-packed.
// BM=128, BN=64, BK=16; 256 threads; per-thread 8 rows x 4 interleaved cols.
//   rows: tr+i (tr = (tid/16)*8), cols: j = tc + 16*jj (tc = tid%16).
// Stride 18 floats: even (8B-aligned LDS.64) and conflict-free for b-loads
// (18*lane mod 32 covers 16 distinct even banks).
// epi: 0 = plain store; 1 = +bias, relu; 2 = +bias +res
#define GS 18
__global__ void gemm_nt(const float* __restrict__ A, const float* __restrict__ W,
                        const float* __restrict__ bias, const float* __restrict__ res,
                        float* __restrict__ C, int epi) {
    __shared__ float As[128 * GS];
    __shared__ float Bs[64 * GS];
    int tid = threadIdx.x;
    int bm = blockIdx.y * 128, bn = blockIdx.x * 64;
    int tr = (tid >> 4) * 8;      // 0..120
    int tc = tid & 15;            // 0..15

    ull acc2[8][4];
    #pragma unroll
    for (int i = 0; i < 8; i++)
        #pragma unroll
        for (int j = 0; j < 4; j++) acc2[i][j] = 0ull;

    for (int k0 = 0; k0 < DD; k0 += 16) {
        #pragma unroll
        for (int l = 0; l < 2; l++) {
            int idx = tid + l * 256;
            int m = idx >> 2, k4 = (idx & 3) * 4;
            float4 tv = *(const float4*)&A[(size_t)(bm + m) * DD + k0 + k4];
            As[m * GS + k4 + 0] = tv.x;
            As[m * GS + k4 + 1] = tv.y;
            As[m * GS + k4 + 2] = tv.z;
            As[m * GS + k4 + 3] = tv.w;
        }
        {
            int n = tid >> 2, k4 = (tid & 3) * 4;
            float4 tv = *(const float4*)&W[(size_t)(bn + n) * DD + k0 + k4];
            Bs[n * GS + k4 + 0] = tv.x;
            Bs[n * GS + k4 + 1] = tv.y;
            Bs[n * GS + k4 + 2] = tv.z;
            Bs[n * GS + k4 + 3] = tv.w;
        }
        __syncthreads();
        #pragma unroll
        for (int kk = 0; kk < 16; kk += 2) {
            ull a2[8], b2[4];
            #pragma unroll
            for (int i = 0; i < 8; i++) a2[i] = *(const ull*)&As[(tr + i) * GS + kk];
            #pragma unroll
            for (int j = 0; j < 4; j++) b2[j] = *(const ull*)&Bs[(tc + 16 * j) * GS + kk];
            #pragma unroll
            for (int i = 0; i < 8; i++)
                #pragma unroll
                for (int j = 0; j < 4; j++) acc2[i][j] = ffma2(a2[i], b2[j], acc2[i][j]);
        }
        __syncthreads();
    }

    #pragma unroll
    for (int i = 0; i < 8; i++) {
        int m = bm + tr + i;
        #pragma unroll
        for (int j = 0; j < 4; j++) {
            int n = bn + tc + 16 * j;
            float v = hsum2(acc2[i][j]);
            if (epi >= 1) v += bias[n];
            if (epi == 1) v = fmaxf(v, 0.f);
            if (epi == 2) v += res[(size_t)m * DD + n];
            C[(size_t)m * DD + n] = v;
        }
    }
}

// Flash attention, causal. One block per (64-row q-tile, b*h). 256 threads.
// Register-blocked 4x4 micro-tile, FFMA2-packed:
//   score phase packs over head-dim pairs; PV packs over output-col pairs.
#define SP 68
__global__ void attn_kernel(const float* __restrict__ q, const float* __restrict__ k,
                            const float* __restrict__ v, float* __restrict__ att) {
    extern __shared__ float sm[];
    float* Qs = sm;
    float* Ks = sm + 64 * SP;
    float* Vs = sm + 2 * 64 * SP;
    float* Ps = sm + 3 * 64 * SP;

    int bh = blockIdx.y;
    int b = bh >> 2, h = bh & 3;
    int qt = 63 - blockIdx.x;  // longest blocks launch first
    int tid = threadIdx.x;
    int ty = tid >> 4;
    int tx = tid & 15;

    const float* qbase = q + (size_t)b * SS * DD + h * HD;
    const float* kbase = k + (size_t)b * SS * DD + h * HD;
    const float* vbase = v + (size_t)b * SS * DD + h * HD;

    for (int l = tid; l < 1024; l += 256) {
        int rr = l >> 4, d4 = (l & 15) * 4;
        float4 tv = *(const float4*)&qbase[(size_t)(qt * 64 + rr) * DD + d4];
        Qs[rr * SP + d4 + 0] = tv.x * INV_TEMP;
        Qs[rr * SP + d4 + 1] = tv.y * INV_TEMP;
        Qs[rr * SP + d4 + 2] = tv.z * INV_TEMP;
        Qs[rr * SP + d4 + 3] = tv.w * INV_TEMP;
    }

    ull acc2[4][2];   // packed output col pairs: (0,1),(2,3) of tx*4+cc
    float m_i[4], l_i[4];
    #pragma unroll
    for (int rr = 0; rr < 4; rr++) {
        m_i[rr] = -INFINITY; l_i[rr] = 0.f;
        acc2[rr][0] = 0ull; acc2[rr][1] = 0ull;
    }

    __syncthreads();

    for (int kt = 0; kt <= qt; kt++) {
        for (int l = tid; l < 1024; l += 256) {
            int rr = l >> 4, d4 = (l & 15) * 4;
            size_t gidx = (size_t)(kt * 64 + rr) * DD + d4;
            float4 kv = *(const float4*)&kbase[gidx];
            float4 vv = *(const float4*)&vbase[gidx];
            Ks[rr * SP + d4 + 0] = kv.x; Ks[rr * SP + d4 + 1] = kv.y;
            Ks[rr * SP + d4 + 2] = kv.z; Ks[rr * SP + d4 + 3] = kv.w;
            Vs[rr * SP + d4 + 0] = vv.x; Vs[rr * SP + d4 + 1] = vv.y;
            Vs[rr * SP + d4 + 2] = vv.z; Vs[rr * SP + d4 + 3] = vv.w;
        }
        __syncthreads();

        // Scores packed over d: s2[rr][c] accumulates (d even, d odd) lanes.
        ull s2[4][4];
        #pragma unroll
        for (int rr = 0; rr < 4; rr++)
            #pragma unroll
            for (int c = 0; c < 4; c++) s2[rr][c] = 0ull;

        #pragma unroll
        for (int d0 = 0; d0 < 64; d0 += 4) {
            ulonglong2 qp[4], kp[4];
            #pragma unroll
            for (int rr = 0; rr < 4; rr++)
                qp[rr] = *(const ulonglong2*)&Qs[(ty * 4 + rr) * SP + d0];
            #pragma unroll
            for (int c = 0; c < 4; c++)
                kp[c] = *(const ulonglong2*)&Ks[(tx + 16 * c) * SP + d0];
            #pragma unroll
            for (int rr = 0; rr < 4; rr++)
                #pragma unroll
                for (int c = 0; c < 4; c++) {
                    s2[rr][c] = ffma2(qp[rr].x, kp[c].x, s2[rr][c]);
                    s2[rr][c] = ffma2(qp[rr].y, kp[c].y, s2[rr][c]);
                }
        }

        float s[4][4];
        #pragma unroll
        for (int rr = 0; rr < 4; rr++)
            #pragma unroll
            for (int c = 0; c < 4; c++) s[rr][c] = hsum2(s2[rr][c]);

        bool diag = (kt == qt);
        #pragma unroll
        for (int rr = 0; rr < 4; rr++) {
            int row = ty * 4 + rr;
            float mx = -INFINITY;
            #pragma unroll
            for (int c = 0; c < 4; c++) {
                int j = tx + 16 * c;
                if (diag && j > row) s[rr][c] = -INFINITY;
                mx = fmaxf(mx, s[rr][c]);
            }
            mx = fmaxf(mx, __shfl_xor_sync(0xffffffffu, mx, 1));
            mx = fmaxf(mx, __shfl_xor_sync(0xffffffffu, mx, 2));
            mx = fmaxf(mx, __shfl_xor_sync(0xffffffffu, mx, 4));
            mx = fmaxf(mx, __shfl_xor_sync(0xffffffffu, mx, 8));
            float m_new = fmaxf(m_i[rr], mx);
            float alpha = __expf(m_i[rr] - m_new);

            float lsum = 0.f;
            #pragma unroll
            for (int c = 0; c < 4; c++) {
                float p = __expf(s[rr][c] - m_new);
                lsum += p;
                Ps[row * SP + tx + 16 * c] = p;
            }
            lsum += __shfl_xor_sync(0xffffffffu, lsum, 1);
            lsum += __shfl_xor_sync(0xffffffffu, lsum, 2);
            lsum += __shfl_xor_sync(0xffffffffu, lsum, 4);
            lsum += __shfl_xor_sync(0xffffffffu, lsum, 8);
            l_i[rr] = l_i[rr] * alpha + lsum;
            m_i[rr] = m_new;
            ull al2 = pack2(alpha, alpha);
            acc2[rr][0] = fmul2(acc2[rr][0], al2);
            acc2[rr][1] = fmul2(acc2[rr][1], al2);
        }

        // P rows for this thread are produced & consumed within the same warp.
        __syncwarp();

        // PV packed over cols: acc2[rr][h2] += P[row][j] * V[j][tx*4 + 2*h2 ..]
        #pragma unroll
        for (int j0 = 0; j0 < 64; j0 += 4) {
            float4 pv[4];
            ulonglong2 vv[4];
            #pragma unroll
            for (int rr = 0; rr < 4; rr++)
                pv[rr] = *(const float4*)&Ps[(ty * 4 + rr) * SP + j0];
            #pragma unroll
            for (int jj = 0; jj < 4; jj++)
                vv[jj] = *(const ulonglong2*)&Vs[(j0 + jj) * SP + tx * 4];
            #pragma unroll
            for (int rr = 0; rr < 4; rr++) {
                const float* pr = &pv[rr].x;
                #pragma unroll
                for (int jj = 0; jj < 4; jj++) {
                    ull pb = pack2(pr[jj], pr[jj]);
                    acc2[rr][0] = ffma2(pb, vv[jj].x, acc2[rr][0]);
                    acc2[rr][1] = ffma2(pb, vv[jj].y, acc2[rr][1]);
                }
            }
        }
        __syncthreads();
    }

    float* obase = att + (size_t)b * SS * DD + h * HD;
    #pragma unroll
    for (int rr = 0; rr < 4; rr++) {
        float inv = 1.f / l_i[rr];
        size_t orow = (size_t)(qt * 64 + ty * 4 + rr) * DD + tx * 4;
        float a0, a1, a2, a3;
        unpack2(acc2[rr][0], a0, a1);
        unpack2(acc2[rr][1], a2, a3);
        float4 o = make_float4(a0 * inv, a1 * inv, a2 * inv, a3 * inv);
        *(float4*)&obase[orow] = o;
    }
}

#define SMEM_ATTN (4 * 64 * SP * 4)

extern "C" void kernel_launch(void* const* d_in, const int* in_sizes, int n_in,
                              void* d_out, int out_size) {
    const float* x   = (const float*)d_in[0];
    const float* Wq  = (const float*)d_in[1];
    const float* Wk  = (const float*)d_in[2];
    const float* Wv  = (const float*)d_in[3];
    const float* g1  = (const float*)d_in[4];
    const float* b1  = (const float*)d_in[5];
    const float* g2  = (const float*)d_in[6];
    const float* b2  = (const float*)d_in[7];
    const float* W1  = (const float*)d_in[8];
    const float* bf1 = (const float*)d_in[9];
    const float* W2  = (const float*)d_in[10];
    const float* bf2 = (const float*)d_in[11];
    float* out = (float*)d_out;

    float *xn, *q, *k, *v, *att, *xt, *h, *a1;
    cudaGetSymbolAddress((void**)&xn,  g_xn);
    cudaGetSymbolAddress((void**)&q,   g_q);
    cudaGetSymbolAddress((void**)&k,   g_k);
    cudaGetSymbolAddress((void**)&v,   g_v);
    cudaGetSymbolAddress((void**)&att, g_att);
    cudaGetSymbolAddress((void**)&xt,  g_xt);
    cudaGetSymbolAddress((void**)&h,   g_h);
    cudaGetSymbolAddress((void**)&a1,  g_a1);

    cudaFuncSetAttribute(attn_kernel, cudaFuncAttributeMaxDynamicSharedMemorySize, SMEM_ATTN);

    // 1. xn = LN(x)
    ln_kernel<<<NN, 256>>>(x, nullptr, g1, b1, nullptr, xn);
    // 2. QKV projections
    gemm_nt<<<dim3(DD / 64, NN / 128), 256>>>(xn, Wq, nullptr, nullptr, q, 0);
    gemm_nt<<<dim3(DD / 64, NN / 128), 256>>>(xn, Wk, nullptr, nullptr, k, 0);
    gemm_nt<<<dim3(DD / 64, NN / 128), 256>>>(xn, Wv, nullptr, nullptr, v, 0);
    // 3. causal flash attention
    attn_kernel<<<dim3(SS / 64, BB * HH), 256, SMEM_ATTN>>>(q, k, v, att);
    // 4. xt = x + att; h = LN(xt)
    ln_kernel<<<NN, 256>>>(x, att, g2, b2, xt, h);
    // 5. a1 = relu(h @ W1^T + bf1)
    gemm_nt<<<dim3(DD / 64, NN / 128), 256>>>(h, W1, bf1, nullptr, a1, 1);
    // 6. out = xt + a1 @ W2^T + bf2
    gemm_nt<<<dim3(DD / 64, NN / 128), 256>>>(a1, W2, bf2, xt, out, 2);
}